// round 15
// baseline (speedup 1.0000x reference)
#include <cuda_runtime.h>

// ---------------------------------------------------------------------------
// RPN pipeline, all fp32 (ordering-sensitive: top-k + greedy NMS).
//   conv3x3+relu (FFMA2 f32x2 packed) -> heads(1x1) -> decode+sigmoid+hist
//   -> radix-select top6000 -> rank-scatter -> clip/valid -> NMS bitmask
//   (triangular) -> batched warp scan -> top-300
// ---------------------------------------------------------------------------

#define NPROP 36864
#define NPRE  6000
#define NPOST 300
#define NW    94        // 6000 bits -> 94 x 64-bit words
#define NSEL  8192      // candidate capacity (top bin adds ~400 over 6000)
#define NBIN  524288    // histogram bins: kd>>12, kd < 2^31
#define NMASKW (NPRE * NW)   // 564000 mask words

__device__ float g_y[512 * 4096];          // conv1 output (relu'd)
__device__ float g_cls[9 * 4096];
__device__ float g_box[36 * 4096];
__device__ float g_preds[NPROP * 4];       // decoded boxes (unclipped)
__device__ float g_sig[NPROP];             // sigmoid scores
__device__ unsigned int g_kd[NPROP];       // descending-monotone score key
__device__ int g_hist[NBIN];
__device__ int g_coarse[1024];
__device__ int g_cut;                      // cutoff bin
__device__ int g_cnt;                      // gather counter
__device__ unsigned long long g_sel[NSEL]; // gathered candidate keys
__device__ unsigned long long g_top[NPRE]; // exact sorted top-6000 keys
__device__ float g_b6k[NPRE * 4];          // clipped boxes of top-6000
__device__ float g_v6k[NPRE];              // sigmoid values of top-6000
__device__ unsigned int g_valid32[192];    // validity bits (ballot words)
__device__ unsigned long long g_mask[NMASKW];
__device__ unsigned long long g_keepbits[NW];

// ---------------------------------------------------------------------------
// f32x2 packed helpers (sm_103a FFMA2 path; each lane = exact fp32 FMA).
// ---------------------------------------------------------------------------
__device__ __forceinline__ unsigned long long ffma2(
    unsigned long long a, unsigned long long b, unsigned long long c)
{
    unsigned long long d;
    asm("fma.rn.f32x2 %0, %1, %2, %3;" : "=l"(d) : "l"(a), "l"(b), "l"(c));
    return d;
}
__device__ __forceinline__ unsigned long long packf2(float lo, float hi)
{
    unsigned long long d;
    asm("mov.b64 %0, {%1, %2};" : "=l"(d) : "f"(lo), "f"(hi));
    return d;
}
__device__ __forceinline__ void unpackf2(unsigned long long v, float& lo, float& hi)
{
    asm("mov.b64 {%0, %1}, %2;" : "=f"(lo), "=f"(hi) : "l"(v));
}

// ---------------------------------------------------------------------------
// memset slices (3 kernels so conv is the 4th launch -> gets profiled).
// ---------------------------------------------------------------------------
__global__ void __launch_bounds__(256) memset_a()
{
    const int idx = blockIdx.x * 256 + threadIdx.x;   // 256 blocks -> 65536
    const int hb = idx * 4;
#pragma unroll
    for (int q = 0; q < 4; ++q) g_hist[hb + q] = 0;    // [0, 262144)
#pragma unroll
    for (int q = 0; q < 5; ++q) {
        int m = idx * 5 + q;                           // [0, 327680) guard
        if (m < NMASKW / 2) g_mask[m] = 0ull;
    }
}

__global__ void __launch_bounds__(256) memset_b()
{
    const int idx = blockIdx.x * 256 + threadIdx.x;
    const int hb = 262144 + idx * 4;
#pragma unroll
    for (int q = 0; q < 4; ++q) g_hist[hb + q] = 0;    // [262144, 524288)
#pragma unroll
    for (int q = 0; q < 5; ++q) {
        int m = NMASKW / 2 + idx * 5 + q;
        if (m < NMASKW) g_mask[m] = 0ull;
    }
}

__global__ void __launch_bounds__(256) memset_c()
{
    const int t = threadIdx.x;                         // 1 block, 256 thr
    if (t == 0) g_cnt = 0;
    if (t < 192) g_valid32[t] = 0u;
#pragma unroll
    for (int q = 0; q < 32; ++q) {
        int i = t * 32 + q;                            // covers NSEL = 8192
        g_sel[i] = 0xFFFFFFFF00000000ull | (unsigned int)i;
    }
}

// ---------------------------------------------------------------------------
// Conv 3x3 (512->512, 64x64, pad 1) + bias + ReLU.  FFMA2 version:
// 64oc x 64px block (one row), BK=8, 128 thr, 8(oc) x 4(px) per thread,
// pixels packed as two f32x2 pairs; weights staged DUPLICATED (w,w) as
// 64-bit so LDS.128 yields 2 splatted ocs. Per-output FMA sequence is
// identical to the validated scalar kernel -> conv output bit-exact.
// ---------------------------------------------------------------------------
__global__ void __launch_bounds__(128) conv3x3_relu(
    const float* __restrict__ x,      // (512,64,64)
    const float* __restrict__ w,      // (512,512,3,3)
    const float* __restrict__ bias)   // (512)
{
    __shared__ float Xs[8 * 3 * 66];                       // [icl][row][col -1..64]
    __shared__ __align__(16) unsigned long long Ws2[72 * 66]; // [tap][oc] dup pairs

    const int yrow = blockIdx.x;           // 0..63
    const int oc0  = blockIdx.y * 64;      // 8 tiles
    const int tid  = threadIdx.x;          // 0..127
    const int tx   = tid & 15;             // pixel group
    const int ty   = tid >> 4;             // oc group 0..7
    const int px0  = tx * 4;
    const int oc_t = ty * 8;

    unsigned long long acc2[8][2];
#pragma unroll
    for (int i = 0; i < 8; ++i) { acc2[i][0] = 0ull; acc2[i][1] = 0ull; }

    for (int ic0 = 0; ic0 < 512; ic0 += 8) {
        // stage X halo: 8 ic x 3 rows x 66 cols
        for (int idx = tid; idx < 8 * 3 * 66; idx += 128) {
            int icl = idx / 198;
            int rem = idx - icl * 198;
            int r   = rem / 66;
            int c   = rem - r * 66 - 1;        // -1..64
            int gy  = yrow - 1 + r;
            float v = 0.f;
            if ((unsigned)gy < 64u && (unsigned)c < 64u)
                v = x[(ic0 + icl) * 4096 + gy * 64 + c];
            Xs[idx] = v;
        }
        // stage W duplicated: Ws2[tap*66+oc] = (w,w)
        for (int idx = tid; idx < 64 * 72; idx += 128) {
            int oc = idx / 72;
            int r  = idx - oc * 72;            // icl*9 + tap
            unsigned int b = __float_as_uint(w[(oc0 + oc) * 4608 + ic0 * 9 + r]);
            Ws2[r * 66 + oc] = ((unsigned long long)b << 32) | b;
        }
        __syncthreads();

#pragma unroll 4
        for (int icl = 0; icl < 8; ++icl) {
#pragma unroll
            for (int kh = 0; kh < 3; ++kh) {
                const int xb = icl * 198 + kh * 66 + px0;
                float x0 = Xs[xb + 0], x1 = Xs[xb + 1], x2 = Xs[xb + 2];
                float x3 = Xs[xb + 3], x4 = Xs[xb + 4], x5 = Xs[xb + 5];
                unsigned long long p01 = packf2(x0, x1);
                unsigned long long p12 = packf2(x1, x2);
                unsigned long long p23 = packf2(x2, x3);
                unsigned long long p34 = packf2(x3, x4);
                unsigned long long p45 = packf2(x4, x5);
#pragma unroll
                for (int kw = 0; kw < 3; ++kw) {
                    const int wb = (icl * 9 + kh * 3 + kw) * 66 + oc_t;
                    const ulonglong2 wq0 = *reinterpret_cast<const ulonglong2*>(&Ws2[wb]);
                    const ulonglong2 wq1 = *reinterpret_cast<const ulonglong2*>(&Ws2[wb + 2]);
                    const ulonglong2 wq2 = *reinterpret_cast<const ulonglong2*>(&Ws2[wb + 4]);
                    const ulonglong2 wq3 = *reinterpret_cast<const ulonglong2*>(&Ws2[wb + 6]);
                    const unsigned long long xa  = (kw == 0) ? p01 : (kw == 1) ? p12 : p23;
                    const unsigned long long xbp = (kw == 0) ? p23 : (kw == 1) ? p34 : p45;
                    acc2[0][0] = ffma2(wq0.x, xa, acc2[0][0]);
                    acc2[0][1] = ffma2(wq0.x, xbp, acc2[0][1]);
                    acc2[1][0] = ffma2(wq0.y, xa, acc2[1][0]);
                    acc2[1][1] = ffma2(wq0.y, xbp, acc2[1][1]);
                    acc2[2][0] = ffma2(wq1.x, xa, acc2[2][0]);
                    acc2[2][1] = ffma2(wq1.x, xbp, acc2[2][1]);
                    acc2[3][0] = ffma2(wq1.y, xa, acc2[3][0]);
                    acc2[3][1] = ffma2(wq1.y, xbp, acc2[3][1]);
                    acc2[4][0] = ffma2(wq2.x, xa, acc2[4][0]);
                    acc2[4][1] = ffma2(wq2.x, xbp, acc2[4][1]);
                    acc2[5][0] = ffma2(wq2.y, xa, acc2[5][0]);
                    acc2[5][1] = ffma2(wq2.y, xbp, acc2[5][1]);
                    acc2[6][0] = ffma2(wq3.x, xa, acc2[6][0]);
                    acc2[6][1] = ffma2(wq3.x, xbp, acc2[6][1]);
                    acc2[7][0] = ffma2(wq3.y, xa, acc2[7][0]);
                    acc2[7][1] = ffma2(wq3.y, xbp, acc2[7][1]);
                }
            }
        }
        __syncthreads();
    }

#pragma unroll
    for (int i = 0; i < 8; ++i) {
        float b = bias[oc0 + oc_t + i];
        float a0, a1, a2, a3;
        unpackf2(acc2[i][0], a0, a1);
        unpackf2(acc2[i][1], a2, a3);
        float* dst = &g_y[(oc0 + oc_t + i) * 4096 + yrow * 64 + px0];
        dst[0] = fmaxf(a0 + b, 0.f);
        dst[1] = fmaxf(a1 + b, 0.f);
        dst[2] = fmaxf(a2 + b, 0.f);
        dst[3] = fmaxf(a3 + b, 0.f);
    }
}

// ---------------------------------------------------------------------------
// 1x1 heads: cls (9) + box (36). VALIDATED R11 SHAPE: 32 blocks x 128 thr.
// ---------------------------------------------------------------------------
__global__ void __launch_bounds__(128) heads_kernel(
    const float* __restrict__ cw, const float* __restrict__ cb,
    const float* __restrict__ bw, const float* __restrict__ bb)
{
    __shared__ float ws[45 * 32];
    const int p = blockIdx.x * 128 + threadIdx.x;
    float acc[45];
#pragma unroll
    for (int c = 0; c < 45; ++c) acc[c] = 0.f;

    for (int ic0 = 0; ic0 < 512; ic0 += 32) {
        for (int idx = threadIdx.x; idx < 45 * 32; idx += 128) {
            int c = idx >> 5, icl = idx & 31;
            ws[idx] = (c < 9) ? cw[c * 512 + ic0 + icl]
                              : bw[(c - 9) * 512 + ic0 + icl];
        }
        __syncthreads();
        for (int icl = 0; icl < 32; ++icl) {
            float v = g_y[(ic0 + icl) * 4096 + p];
#pragma unroll
            for (int c = 0; c < 45; ++c) acc[c] += ws[c * 32 + icl] * v;
        }
        __syncthreads();
    }
#pragma unroll
    for (int a = 0; a < 9; ++a)  g_cls[a * 4096 + p] = acc[a] + cb[a];
#pragma unroll
    for (int c = 0; c < 36; ++c) g_box[c * 4096 + p] = acc[9 + c] + bb[c];
}

// ---------------------------------------------------------------------------
// Decode boxes (exact reshape(-1,4) aliasing), sigmoid, key + histogram.
// ---------------------------------------------------------------------------
__global__ void decode_kernel(const float* __restrict__ anchors)
{
    const int g = blockIdx.x * 256 + threadIdx.x;      // 144*256 == NPROP
    const int c  = g >> 10;
    const int p0 = (g & 1023) << 2;
    float dx = g_box[c * 4096 + p0 + 0];
    float dy = g_box[c * 4096 + p0 + 1];
    float dw = g_box[c * 4096 + p0 + 2];
    float dh = g_box[c * 4096 + p0 + 3];
    float ax1 = anchors[g * 4 + 0], ay1 = anchors[g * 4 + 1];
    float ax2 = anchors[g * 4 + 2], ay2 = anchors[g * 4 + 3];
    float aw = ax2 - ax1, ah = ay2 - ay1;
    float ax = ax1 + 0.5f * aw, ay = ay1 + 0.5f * ah;
    const float BBOX_CLIP = 4.135166556742356f;   // log(1000/16)
    dw = fminf(dw, BBOX_CLIP);
    dh = fminf(dh, BBOX_CLIP);
    float px = dx * aw + ax, py = dy * ah + ay;
    float pw = expf(dw) * aw, ph = expf(dh) * ah;
    g_preds[g * 4 + 0] = px - 0.5f * pw;
    g_preds[g * 4 + 1] = py - 0.5f * ph;
    g_preds[g * 4 + 2] = px + 0.5f * pw;
    g_preds[g * 4 + 3] = py + 0.5f * ph;

    float s = 1.f / (1.f + expf(-g_cls[g]));
    g_sig[g] = s;
    unsigned int u = __float_as_uint(s);
    u ^= (u & 0x80000000u) ? 0xFFFFFFFFu : 0x80000000u;   // ascending-monotone
    unsigned int kd = ~u;                                  // descending
    g_kd[g] = kd;
    atomicAdd(&g_hist[kd >> 12], 1);
}

// ---------------------------------------------------------------------------
// Coarse histogram sums: 1024 chunks of 512 bins.
// ---------------------------------------------------------------------------
__global__ void __launch_bounds__(256) hist_coarse()
{
    __shared__ int sred[256];
    const int b = blockIdx.x, t = threadIdx.x;
    int v = g_hist[b * 512 + t] + g_hist[b * 512 + 256 + t];
    sred[t] = v;
    __syncthreads();
    for (int d = 128; d > 0; d >>= 1) {
        if (t < d) sred[t] += sred[t + d];
        __syncthreads();
    }
    if (t == 0) g_coarse[b] = sred[0];
}

// ---------------------------------------------------------------------------
// Find cutoff bin: first bin B with cumulative(kd ascending) >= NPRE.
// ---------------------------------------------------------------------------
__global__ void __launch_bounds__(1024) findbin_kernel()
{
    __shared__ int s[1024];
    __shared__ int selblk, selbase;
    const int t = threadIdx.x;

    s[t] = g_coarse[t];
    __syncthreads();
    for (int d = 1; d < 1024; d <<= 1) {
        int v = s[t];
        int add = (t >= d) ? s[t - d] : 0;
        __syncthreads();
        s[t] = v + add;
        __syncthreads();
    }
    {
        int cum = s[t];
        int prev = (t == 0) ? 0 : s[t - 1];
        if (cum >= NPRE && prev < NPRE) { selblk = t; selbase = prev; }
    }
    __syncthreads();
    const int bb = selblk, base = selbase;

    __syncthreads();
    s[t] = (t < 512) ? g_hist[bb * 512 + t] : 0;
    __syncthreads();
    for (int d = 1; d < 1024; d <<= 1) {
        int v = s[t];
        int add = (t >= d) ? s[t - d] : 0;
        __syncthreads();
        s[t] = v + add;
        __syncthreads();
    }
    if (t < 512) {
        int cum = base + s[t];
        int prev = base + ((t == 0) ? 0 : s[t - 1]);
        if (cum >= NPRE && prev < NPRE) g_cut = bb * 512 + t;
    }
}

// ---------------------------------------------------------------------------
// Gather all items in bins <= cut (superset of exact top-6000).
// ---------------------------------------------------------------------------
__global__ void gather_kernel()
{
    const int g = blockIdx.x * 256 + threadIdx.x;      // == NPROP threads
    const unsigned int kd = g_kd[g];
    if ((int)(kd >> 12) <= g_cut) {
        int pos = atomicAdd(&g_cnt, 1);
        if (pos < NSEL)
            g_sel[pos] = ((unsigned long long)kd << 32) | (unsigned int)g;
    }
}

// ---------------------------------------------------------------------------
// Rank-by-counting over the <=8192 candidates; scatter ranks < 6000.
// ---------------------------------------------------------------------------
__global__ void __launch_bounds__(256) rank_scatter()
{
    __shared__ unsigned long long sk[2048];
    const int t = blockIdx.x * 256 + threadIdx.x;      // 32 blocks -> 8192
    const unsigned long long my = g_sel[t];
    int r = 0;
    for (int c0 = 0; c0 < NSEL; c0 += 2048) {
        for (int j = threadIdx.x; j < 2048; j += 256) sk[j] = g_sel[c0 + j];
        __syncthreads();
#pragma unroll 8
        for (int j = 0; j < 2048; ++j) r += (sk[j] < my) ? 1 : 0;
        __syncthreads();
    }
    if (r < NPRE) g_top[r] = my;
}

// ---------------------------------------------------------------------------
// Gather top-6000: clip to image, validity bits (ballot), score.
// ---------------------------------------------------------------------------
__global__ void __launch_bounds__(256) post_topk(const int* __restrict__ img)
{
    const int t = blockIdx.x * 256 + threadIdx.x;      // 24 blocks -> 6144
    bool valid = false;
    if (t < NPRE) {
        const unsigned long long key = g_top[t];
        const int g = (int)(key & 0xFFFFFFFFull);
        const float himg = (float)img[0], wimg = (float)img[1];
        float x1 = fminf(fmaxf(g_preds[g * 4 + 0], 0.f), wimg);
        float y1 = fminf(fmaxf(g_preds[g * 4 + 1], 0.f), himg);
        float x2 = fminf(fmaxf(g_preds[g * 4 + 2], 0.f), wimg);
        float y2 = fminf(fmaxf(g_preds[g * 4 + 3], 0.f), himg);
        g_b6k[t * 4 + 0] = x1;
        g_b6k[t * 4 + 1] = y1;
        g_b6k[t * 4 + 2] = x2;
        g_b6k[t * 4 + 3] = y2;
        g_v6k[t] = g_sig[g];
        valid = ((x2 - x1) >= 16.f) && ((y2 - y1) >= 16.f);
    }
    unsigned int bal = __ballot_sync(0xFFFFFFFFu, valid);
    if ((threadIdx.x & 31) == 0) g_valid32[t >> 5] = bal;
}

// ---------------------------------------------------------------------------
// NMS suppression bitmask, TRIANGULAR (g_mask pre-zeroed).
// mask[i][cb] bit jj set iff j>i and IoU(i,j)>0.7.
// ---------------------------------------------------------------------------
__global__ void __launch_bounds__(64) nms_mask()
{
    __shared__ float cbox[64 * 4];
    const int cb = blockIdx.x, rb = blockIdx.y;
    if (cb < rb) return;                   // lower triangle: all-zero words
    const int cbase = cb * 64;
    const int ccount = min(64, NPRE - cbase);
    if ((int)threadIdx.x < ccount) {
#pragma unroll
        for (int q = 0; q < 4; ++q)
            cbox[threadIdx.x * 4 + q] = g_b6k[(cbase + threadIdx.x) * 4 + q];
    }
    __syncthreads();
    const int i = rb * 64 + threadIdx.x;
    if (i >= NPRE) return;
    const float x1 = g_b6k[i * 4 + 0], y1 = g_b6k[i * 4 + 1];
    const float x2 = g_b6k[i * 4 + 2], y2 = g_b6k[i * 4 + 3];
    const float area_i = (x2 - x1) * (y2 - y1);
    unsigned long long bits = 0ull;
    for (int jj = 0; jj < ccount; ++jj) {
        int j = cbase + jj;
        if (j <= i) continue;
        float bx1 = cbox[jj * 4 + 0], by1 = cbox[jj * 4 + 1];
        float bx2 = cbox[jj * 4 + 2], by2 = cbox[jj * 4 + 3];
        float ix1 = fmaxf(x1, bx1), iy1 = fmaxf(y1, by1);
        float ix2 = fminf(x2, bx2), iy2 = fminf(y2, by2);
        float iw = fmaxf(ix2 - ix1, 0.f), ih = fmaxf(iy2 - iy1, 0.f);
        float inter = iw * ih;
        float uni = area_i + (bx2 - bx1) * (by2 - by1) - inter;
        float iou = (uni > 0.f) ? (inter / uni) : 0.f;
        if (iou > 0.7f) bits |= (1ull << jj);
    }
    g_mask[i * NW + cb] = bits;
}

// ---------------------------------------------------------------------------
// Greedy scan: single warp, removed-bits in registers, 8-deep prefetch,
// BATCHED aliveness (validated R14): all 8 rows of a batch live in one rem
// word (8|64); intra-batch greedy resolved locally, one shfl per batch.
// ---------------------------------------------------------------------------
__device__ __forceinline__ void scan_load8(
    unsigned long long (&buf)[8][3], int rowbase, int lane)
{
#pragma unroll
    for (int r = 0; r < 8; ++r) {
        const int i = rowbase + r;
        const bool ok = (i < NPRE);
        const unsigned long long* p = g_mask + (size_t)i * NW;
        buf[r][0] = ok ? p[lane] : 0ull;
        buf[r][1] = ok ? p[lane + 32] : 0ull;
        buf[r][2] = (ok && lane < 30) ? p[lane + 64] : 0ull;
    }
}

__device__ __forceinline__ void scan_proc8(
    const unsigned long long (&buf)[8][3], int base, int lane,
    unsigned long long (&rem)[3], unsigned long long (&keepw)[3])
{
    const int w    = base >> 6;            // same word for all 8 rows (8|64)
    const int src  = w & 31;
    const int slot = w >> 5;
    const int b0   = base & 63;

    unsigned long long localw = (slot == 0) ? rem[0]
                              : (slot == 1) ? rem[1] : rem[2];
    unsigned int am = 0;
#pragma unroll
    for (int r = 0; r < 8; ++r) {
        if (((localw >> (b0 + r)) & 1ull) == 0ull) {
            am |= (1u << r);
            localw |= (slot == 0) ? buf[r][0]
                    : (slot == 1) ? buf[r][1] : buf[r][2];
        }
    }
    am = __shfl_sync(0xFFFFFFFFu, am, src);

#pragma unroll
    for (int r = 0; r < 8; ++r) {
        if ((am >> r) & 1u) {
            rem[0] |= buf[r][0];
            rem[1] |= buf[r][1];
            rem[2] |= buf[r][2];
        }
    }
    if (lane == src) {
        if (slot == 0)      keepw[0] |= (unsigned long long)am << b0;
        else if (slot == 1) keepw[1] |= (unsigned long long)am << b0;
        else                keepw[2] |= (unsigned long long)am << b0;
    }
}

__global__ void __launch_bounds__(32) nms_scan_warp()
{
    const int lane = threadIdx.x;
    unsigned long long rem[3], keepw[3] = {0ull, 0ull, 0ull};
#pragma unroll
    for (int s = 0; s < 3; ++s) {
        const int w = lane + 32 * s;
        if (w < NW) {
            unsigned long long lo = g_valid32[2 * w];
            unsigned long long hi = g_valid32[2 * w + 1];
            rem[s] = ~((hi << 32) | lo);
        } else {
            rem[s] = ~0ull;
        }
    }
    unsigned long long A[8][3], B[8][3];
    scan_load8(A, 0, lane);
    for (int base = 0; base < NPRE; base += 16) {
        scan_load8(B, base + 8, lane);
        scan_proc8(A, base, lane, rem, keepw);
        scan_load8(A, base + 16, lane);
        scan_proc8(B, base + 8, lane, rem, keepw);
    }
#pragma unroll
    for (int s = 0; s < 3; ++s) {
        const int w = lane + 32 * s;
        if (w < NW) g_keepbits[w] = keepw[s];
    }
}

// ---------------------------------------------------------------------------
// Finalize: kept entries in order, then suppressed by ascending index with
// score -1; first 300 -> out (boxes [300,4] then scores [300]).
// ---------------------------------------------------------------------------
__global__ void __launch_bounds__(256) finalize(float* __restrict__ out)
{
    __shared__ int ckeep[256], csupp[256];
    __shared__ int okeep[256], osupp[256];
    __shared__ int totk;
    const int t = threadIdx.x;
    const int beg = t * 24;
    const int end = min(beg + 24, NPRE);
    int ck = 0;
    for (int i = beg; i < end; ++i)
        ck += (int)((g_keepbits[i >> 6] >> (i & 63)) & 1ull);
    ckeep[t] = ck;
    csupp[t] = (end > beg ? (end - beg) : 0) - ck;
    __syncthreads();
    if (t == 0) {
        int a = 0, b = 0;
        for (int q = 0; q < 256; ++q) {
            okeep[q] = a; osupp[q] = b;
            a += ckeep[q]; b += csupp[q];
        }
        totk = a;
    }
    __syncthreads();
    int rk = okeep[t];
    int rs = totk + osupp[t];
    for (int i = beg; i < end; ++i) {
        bool kp = ((g_keepbits[i >> 6] >> (i & 63)) & 1ull) != 0ull;
        int rank = kp ? (rk++) : (rs++);
        if (rank < NPOST) {
            out[rank * 4 + 0] = g_b6k[i * 4 + 0];
            out[rank * 4 + 1] = g_b6k[i * 4 + 1];
            out[rank * 4 + 2] = g_b6k[i * 4 + 2];
            out[rank * 4 + 3] = g_b6k[i * 4 + 3];
            out[NPOST * 4 + rank] = kp ? g_v6k[i] : -1.0f;
        }
    }
}

// ---------------------------------------------------------------------------
extern "C" void kernel_launch(void* const* d_in, const int* in_sizes, int n_in,
                              void* d_out, int out_size)
{
    const float* feature = (const float*)d_in[0];   // (1,512,64,64)
    const float* anchors = (const float*)d_in[1];   // (36864,4)
    const int*   imgsh   = (const int*)d_in[2];     // (2,)
    const float* c1w     = (const float*)d_in[3];   // (512,512,3,3)
    const float* c1b     = (const float*)d_in[4];   // (512,)
    const float* clsw    = (const float*)d_in[5];   // (9,512,1,1)
    const float* clsb    = (const float*)d_in[6];   // (9,)
    const float* boxw    = (const float*)d_in[7];   // (36,512,1,1)
    const float* boxb    = (const float*)d_in[8];   // (36,)
    float* out = (float*)d_out;                     // 1500 floats

    memset_a<<<256, 256>>>();                       // launch 1
    memset_b<<<256, 256>>>();                       // launch 2
    memset_c<<<1, 256>>>();                         // launch 3
    conv3x3_relu<<<dim3(64, 8), 128>>>(feature, c1w, c1b);   // launch 4 (profiled)
    heads_kernel<<<32, 128>>>(clsw, clsb, boxw, boxb);
    decode_kernel<<<NPROP / 256, 256>>>(anchors);
    hist_coarse<<<1024, 256>>>();
    findbin_kernel<<<1, 1024>>>();
    gather_kernel<<<NPROP / 256, 256>>>();
    rank_scatter<<<NSEL / 256, 256>>>();
    post_topk<<<24, 256>>>(imgsh);
    nms_mask<<<dim3(NW, NW), 64>>>();
    nms_scan_warp<<<1, 32>>>();
    finalize<<<1, 256>>>(out);
}